// round 15
// baseline (speedup 1.0000x reference)
#include <cuda_runtime.h>
#include <cuda_bf16.h>
#include <math.h>
#include <stddef.h>
#include <stdint.h>

// Problem dimensions (fixed by the reference)
#define Bz   4
#define Sz   2048
#define Dz   1024
#define Hz   16
#define DKz  64
#define DFFz 4096
#define Mz   (Bz * Sz)   // 8192 rows
#define QS   (3 * Dz)    // fused qkv row stride

// ---------------------------------------------------------------------------
// Scratch buffers. bf16x3 split GEMM along K':
//   A logical [M, 3K] = [Ah | Ah | Al], stored as TWO planes hi[M,K], lo[M,K]
//   B expanded [3K, N] = [Bh ; Bl ; Bh]  (weights, materialized)
// ---------------------------------------------------------------------------
static __device__ __nv_bfloat16 g_h1x[(size_t)Mz * 3 * Dz];     // 2 planes used
static __device__ float         g_qkv[(size_t)Mz * 3 * Dz];
static __device__ __nv_bfloat16 g_atx[(size_t)Mz * 3 * Dz];     // 2 planes used
static __device__ float         g_x2 [(size_t)Mz * Dz];
static __device__ __nv_bfloat16 g_h2x[(size_t)Mz * 3 * Dz];     // 2 planes used
static __device__ __nv_bfloat16 g_f1x[(size_t)Mz * 3 * DFFz];   // 2 planes used
static __device__ __nv_bfloat16 g_wqkvx[(size_t)(3 * Dz) * (3 * Dz)];
static __device__ __nv_bfloat16 g_wox[(size_t)(3 * Dz) * Dz];
static __device__ __nv_bfloat16 g_w1x[(size_t)(3 * Dz) * DFFz];
static __device__ __nv_bfloat16 g_w2x[(size_t)(3 * DFFz) * Dz];

// ---------------------------------------------------------------------------
// helpers
// ---------------------------------------------------------------------------
__device__ __forceinline__ float gelu_exact(float x)
{
    return 0.5f * x * (1.0f + erff(x * 0.70710678118654752440f));
}

__device__ __forceinline__ void split2(float y0, float y1,
                                       __nv_bfloat162& hh, __nv_bfloat162& ll)
{
    __nv_bfloat16 h0 = __float2bfloat16(y0);
    __nv_bfloat16 h1 = __float2bfloat16(y1);
    __nv_bfloat16 l0 = __float2bfloat16(y0 - __bfloat162float(h0));
    __nv_bfloat16 l1 = __float2bfloat16(y1 - __bfloat162float(h1));
    hh = __halves2bfloat162(h0, h1);
    ll = __halves2bfloat162(l0, l1);
}

__device__ __forceinline__ void split_pack(float a, float b, unsigned& hi, unsigned& lo)
{
    __nv_bfloat16 ha = __float2bfloat16(a);
    __nv_bfloat16 hb = __float2bfloat16(b);
    float ra = a - __bfloat162float(ha);
    float rb = b - __bfloat162float(hb);
    __nv_bfloat162 th = __halves2bfloat162(ha, hb);
    __nv_bfloat162 tl = __halves2bfloat162(__float2bfloat16(ra), __float2bfloat16(rb));
    hi = *(unsigned*)&th;
    lo = *(unsigned*)&tl;
}

__device__ __forceinline__ void ldsm_x4(unsigned* r, uint32_t addr)
{
    asm volatile("ldmatrix.sync.aligned.m8n8.x4.shared.b16 {%0,%1,%2,%3}, [%4];\n"
                 : "=r"(r[0]), "=r"(r[1]), "=r"(r[2]), "=r"(r[3]) : "r"(addr));
}
__device__ __forceinline__ void ldsm_x4_t(unsigned* r, uint32_t addr)
{
    asm volatile("ldmatrix.sync.aligned.m8n8.x4.trans.shared.b16 {%0,%1,%2,%3}, [%4];\n"
                 : "=r"(r[0]), "=r"(r[1]), "=r"(r[2]), "=r"(r[3]) : "r"(addr));
}
__device__ __forceinline__ void mma_bf16(float* d, const unsigned* a,
                                         const unsigned* b, const float* c)
{
    asm volatile(
        "mma.sync.aligned.m16n8k16.row.col.f32.bf16.bf16.f32 "
        "{%0,%1,%2,%3}, {%4,%5,%6,%7}, {%8,%9}, {%10,%11,%12,%13};\n"
        : "=f"(d[0]), "=f"(d[1]), "=f"(d[2]), "=f"(d[3])
        : "r"(a[0]), "r"(a[1]), "r"(a[2]), "r"(a[3]), "r"(b[0]), "r"(b[1]),
          "f"(c[0]), "f"(c[1]), "f"(c[2]), "f"(c[3]));
}
__device__ __forceinline__ void cp_async16(uint32_t dst, const void* src)
{
    asm volatile("cp.async.cg.shared.global [%0], [%1], 16;\n"
                 :: "r"(dst), "l"(src) : "memory");
}
__device__ __forceinline__ void cp_commit()
{
    asm volatile("cp.async.commit_group;\n" ::: "memory");
}

// ---------------------------------------------------------------------------
// Weight expansion into a sub-block of a wide matrix:
// W[K,N] fp32 -> Wx[(3K) x ldN] bf16 at column offset n0, segments [hi;lo;hi]
// ---------------------------------------------------------------------------
__global__ __launch_bounds__(256)
void wexpand_kernel(const float* __restrict__ W, __nv_bfloat16* __restrict__ Wx,
                    int K, int N, int ldN, int n0)
{
    size_t idx = (size_t)blockIdx.x * blockDim.x + threadIdx.x;
    size_t total = ((size_t)K * N) >> 2;
    if (idx >= total) return;
    size_t e = idx << 2;
    int k = (int)(e / N);
    int n = (int)(e % N) + n0;
    float4 w = *(const float4*)(W + e);
    __nv_bfloat162 hh0, ll0, hh1, ll1;
    split2(w.x, w.y, hh0, ll0);
    split2(w.z, w.w, hh1, ll1);
    size_t b0 = (size_t)k * ldN + n;
    size_t b1 = ((size_t)K + k) * ldN + n;
    size_t b2 = ((size_t)2 * K + k) * ldN + n;
    *(__nv_bfloat162*)(Wx + b0)     = hh0;
    *(__nv_bfloat162*)(Wx + b0 + 2) = hh1;
    *(__nv_bfloat162*)(Wx + b1)     = ll0;
    *(__nv_bfloat162*)(Wx + b1 + 2) = ll1;
    *(__nv_bfloat162*)(Wx + b2)     = hh0;
    *(__nv_bfloat162*)(Wx + b2 + 2) = hh1;
}

// ---------------------------------------------------------------------------
// LayerNorm + split: out 2 planes hi[M,D], lo[M,D]
// ---------------------------------------------------------------------------
__global__ __launch_bounds__(256)
void ln_split_kernel(const float* __restrict__ x, const float* __restrict__ g,
                     const float* __restrict__ bt,
                     __nv_bfloat16* __restrict__ outH, __nv_bfloat16* __restrict__ outL)
{
    const int row = blockIdx.x;
    const int tid = threadIdx.x;
    const float4* xr = (const float4*)(x + (size_t)row * Dz);
    float4 v = xr[tid];

    float s  = v.x + v.y + v.z + v.w;
    float s2 = v.x * v.x + v.y * v.y + v.z * v.z + v.w * v.w;
    #pragma unroll
    for (int o = 16; o > 0; o >>= 1) {
        s  += __shfl_xor_sync(0xffffffffu, s,  o);
        s2 += __shfl_xor_sync(0xffffffffu, s2, o);
    }
    __shared__ float ws[8], ws2[8];
    const int wid = tid >> 5, lane = tid & 31;
    if (lane == 0) { ws[wid] = s; ws2[wid] = s2; }
    __syncthreads();
    __shared__ float s_mean, s_inv;
    if (tid == 0) {
        float a = 0.f, b = 0.f;
        #pragma unroll
        for (int i = 0; i < 8; i++) { a += ws[i]; b += ws2[i]; }
        float mean = a * (1.0f / Dz);
        float var  = b * (1.0f / Dz) - mean * mean;
        s_mean = mean;
        s_inv  = rsqrtf(var + 1e-5f);
    }
    __syncthreads();
    const float mean = s_mean, inv = s_inv;

    float4 gg = ((const float4*)g)[tid];
    float4 bb = ((const float4*)bt)[tid];
    float y0 = (v.x - mean) * inv * gg.x + bb.x;
    float y1 = (v.y - mean) * inv * gg.y + bb.y;
    float y2 = (v.z - mean) * inv * gg.z + bb.z;
    float y3 = (v.w - mean) * inv * gg.w + bb.w;

    __nv_bfloat162 hh0, ll0, hh1, ll1;
    split2(y0, y1, hh0, ll0);
    split2(y2, y3, hh1, ll1);
    const size_t o = (size_t)row * Dz + tid * 4;
    *(__nv_bfloat162*)(outH + o)     = hh0;
    *(__nv_bfloat162*)(outH + o + 2) = hh1;
    *(__nv_bfloat162*)(outL + o)     = ll0;
    *(__nv_bfloat162*)(outL + o + 2) = ll1;
}

// ---------------------------------------------------------------------------
// bf16 tensor-core GEMM v8 (R7 loop, 2-plane A addressing):
// CTA tile 128x128, 128 threads (4 warps, 2Mx2N), warp tile 64x64, BK=32,
// 4-stage cp.async ring, 2 CTAs/SM, two barriers per K-iteration.
// Logical A[M, 3*Kseg] = [Ah | Ah | Al]; loader maps k' to the hi/lo plane.
// OUTMODE 0: fp32 C (+bias)(+gelu)(+res)
// OUTMODE 2: split bf16 planes: hi -> Cout, lo -> Cout2 (both [M,N])
// ---------------------------------------------------------------------------
#define V4_STAGES 4
#define V4_ASTAGE 8192
#define V4_STAGE  16384
#define V4_SMEM   (V4_STAGES * V4_STAGE + 1024)   // 66560

template<int OUTMODE, bool GELU, bool BIAS, bool RES>
__global__ __launch_bounds__(128, 2)
void gemm_bf16_v8(const __nv_bfloat16* __restrict__ Ah, const __nv_bfloat16* __restrict__ Al,
                  const __nv_bfloat16* __restrict__ B,
                  const float* __restrict__ bias, const float* __restrict__ res,
                  void* __restrict__ Cout, void* __restrict__ Cout2,
                  int Ni, int Kseg)
{
    extern __shared__ char dsm[];
    const uint32_t base0 = ((uint32_t)__cvta_generic_to_shared(dsm) + 1023u) & ~1023u;

    const int tid = threadIdx.x;
    const int lane = tid & 31;
    const int wid = tid >> 5;
    const int warp_m = wid & 1;
    const int warp_n = wid >> 1;
    const int bm = blockIdx.y * 128;
    const int bn = blockIdx.x * 128;

    const int l7  = lane & 7;
    const int l8  = (lane >> 3) & 1;
    const int l16 = lane >> 4;

    float acc[4][8][4];
    #pragma unroll
    for (int mt = 0; mt < 4; mt++)
        #pragma unroll
        for (int nt = 0; nt < 8; nt++)
            #pragma unroll
            for (int i = 0; i < 4; i++) acc[mt][nt][i] = 0.f;

    const int Kp = 3 * Kseg;

    auto load_stage = [&](int kt) {
        const uint32_t base = base0 + (kt & (V4_STAGES - 1)) * V4_STAGE;
        // A plane selection: k' = kt*32; [0,2K)->Ah (mod K), [2K,3K)->Al
        const int kb = kt * 32;
        const __nv_bfloat16* Asrc;
        int kof;
        if (kb < 2 * Kseg) { Asrc = Ah; kof = (kb >= Kseg) ? kb - Kseg : kb; }
        else               { Asrc = Al; kof = kb - 2 * Kseg; }
        #pragma unroll
        for (int i = 0; i < 4; i++) {
            int idx = i * 128 + tid;
            int m = idx >> 2, c = idx & 3;
            const void* src = Asrc + (size_t)(bm + m) * Kseg + kof + c * 8;
            cp_async16(base + (m << 6) + ((c ^ ((m >> 1) & 3)) << 4), src);
        }
        #pragma unroll
        for (int i = 0; i < 4; i++) {
            int idx = i * 128 + tid;
            int k = idx >> 4, c = idx & 15;
            const void* src = B + (size_t)(kt * 32 + k) * Ni + bn + c * 8;
            cp_async16(base + V4_ASTAGE + (k << 8) + ((c ^ (k & 7)) << 4), src);
        }
        cp_commit();
    };

    const int NK = Kp / 32;
    load_stage(0); load_stage(1); load_stage(2);

    for (int kt = 0; kt < NK; kt++) {
        if (kt + 3 < NK) load_stage(kt + 3);
        const int rem = NK - 1 - kt;
        if (rem >= 3)      asm volatile("cp.async.wait_group 3;\n" ::: "memory");
        else if (rem == 2) asm volatile("cp.async.wait_group 2;\n" ::: "memory");
        else if (rem == 1) asm volatile("cp.async.wait_group 1;\n" ::: "memory");
        else               asm volatile("cp.async.wait_group 0;\n" ::: "memory");
        __syncthreads();

        const uint32_t sa = base0 + (kt & (V4_STAGES - 1)) * V4_STAGE;
        const uint32_t sb = sa + V4_ASTAGE;
        #pragma unroll
        for (int ks = 0; ks < 2; ks++) {
            unsigned ra[4][4], rb[4][4];
            #pragma unroll
            for (int mt = 0; mt < 4; mt++) {
                int row = warp_m * 64 + mt * 16 + l7 + l8 * 8;
                int c   = ks * 2 + l16;
                ldsm_x4(ra[mt], sa + (row << 6) + ((c ^ ((row >> 1) & 3)) << 4));
            }
            #pragma unroll
            for (int p = 0; p < 4; p++) {
                int k = ks * 16 + l7 + l8 * 8;
                int c = warp_n * 8 + p * 2 + l16;
                ldsm_x4_t(rb[p], sb + (k << 8) + ((c ^ (k & 7)) << 4));
            }
            #pragma unroll
            for (int mt = 0; mt < 4; mt++)
                #pragma unroll
                for (int nt = 0; nt < 8; nt++)
                    mma_bf16(acc[mt][nt], ra[mt], &rb[nt >> 1][(nt & 1) * 2], acc[mt][nt]);
        }
        __syncthreads();
    }

    // epilogue
    const int g = lane >> 2, t = lane & 3;
    #pragma unroll
    for (int mt = 0; mt < 4; mt++) {
        #pragma unroll
        for (int nt = 0; nt < 8; nt++) {
            const int col = bn + warp_n * 64 + nt * 8 + 2 * t;
            #pragma unroll
            for (int half = 0; half < 2; half++) {
                const int r = bm + warp_m * 64 + mt * 16 + g + half * 8;
                float v0 = acc[mt][nt][half * 2 + 0];
                float v1 = acc[mt][nt][half * 2 + 1];
                if (BIAS) { v0 += bias[col]; v1 += bias[col + 1]; }
                if (GELU) { v0 = gelu_exact(v0); v1 = gelu_exact(v1); }
                if (RES) {
                    const float* rp = res + (size_t)r * Ni + col;
                    v0 += rp[0]; v1 += rp[1];
                }
                if (OUTMODE == 0) {
                    float2 o; o.x = v0; o.y = v1;
                    *(float2*)((float*)Cout + (size_t)r * Ni + col) = o;
                } else {
                    __nv_bfloat162 hh, ll;
                    split2(v0, v1, hh, ll);
                    size_t b = (size_t)r * Ni + col;
                    *(__nv_bfloat162*)((__nv_bfloat16*)Cout  + b) = hh;
                    *(__nv_bfloat162*)((__nv_bfloat16*)Cout2 + b) = ll;
                }
            }
        }
    }
}

// ---------------------------------------------------------------------------
// Tensor-core causal flash attention (bf16x3 split, fp32 softmax).
// 64 queries per CTA (4 warps), K/V tiles of 64 keys.
// Reads fused qkv [M, 3D] fp32. Writes 2-plane bf16 output (hi, lo).
// ---------------------------------------------------------------------------
__global__ __launch_bounds__(128)
void attn_mma_kernel(const float* __restrict__ QKV,
                     __nv_bfloat16* __restrict__ OH, __nv_bfloat16* __restrict__ OL)
{
    const int qt  = (gridDim.x - 1) - blockIdx.x;
    const int bh  = blockIdx.y;
    const int b   = bh >> 4;
    const int h   = bh & 15;
    const int tid = threadIdx.x;
    const int w   = tid >> 5;
    const int lane = tid & 31;
    const int g   = lane >> 2;
    const int t4  = lane & 3;
    const int l7  = lane & 7;

    __shared__ __align__(128) __nv_bfloat16 sKh[64 * 64];
    __shared__ __align__(128) __nv_bfloat16 sKl[64 * 64];
    __shared__ __align__(128) __nv_bfloat16 sVh[64 * 64];
    __shared__ __align__(128) __nv_bfloat16 sVl[64 * 64];
    const uint32_t aKh = (uint32_t)__cvta_generic_to_shared(sKh);
    const uint32_t aKl = (uint32_t)__cvta_generic_to_shared(sKl);
    const uint32_t aVh = (uint32_t)__cvta_generic_to_shared(sVh);
    const uint32_t aVl = (uint32_t)__cvta_generic_to_shared(sVl);

    unsigned qh[4][4], ql[4][4];
    {
        const float* Qw = QKV + ((size_t)(b * Sz + qt * 64 + w * 16)) * QS + h * DKz;
        #pragma unroll
        for (int ko = 0; ko < 4; ko++) {
            #pragma unroll
            for (int rh = 0; rh < 2; rh++) {
                const float* rp = Qw + (size_t)(rh * 8 + g) * QS + ko * 16 + 2 * t4;
                float2 lo = *(const float2*)rp;
                float2 hi = *(const float2*)(rp + 8);
                split_pack(lo.x * 0.125f, lo.y * 0.125f, qh[ko][rh],     ql[ko][rh]);
                split_pack(hi.x * 0.125f, hi.y * 0.125f, qh[ko][2 + rh], ql[ko][2 + rh]);
            }
        }
    }

    float out[8][4];
    #pragma unroll
    for (int nd = 0; nd < 8; nd++)
        #pragma unroll
        for (int i = 0; i < 4; i++) out[nd][i] = 0.f;
    float m0 = -1e30f, m1 = -1e30f, l0 = 0.f, l1 = 0.f;

    const float* Kb = QKV + ((size_t)(b * Sz)) * QS + Dz + h * DKz;
    const float* Vb = QKV + ((size_t)(b * Sz)) * QS + 2 * Dz + h * DKz;

    for (int kt = 0; kt <= qt; kt++) {
        __syncthreads();
        const float* Kt = Kb + (size_t)kt * 64 * QS;
        const float* Vt = Vb + (size_t)kt * 64 * QS;
        #pragma unroll
        for (int i = 0; i < 8; i++) {
            int idx = i * 128 + tid;
            int row = idx >> 4, c4 = idx & 15;
            const size_t go = (size_t)row * QS + c4 * 4;
            float4 kv = *(const float4*)(Kt + go);
            float4 vv = *(const float4*)(Vt + go);
            uint32_t off = (row << 7) + ((((c4 >> 1) ^ (row & 7)) << 4)) + ((c4 & 1) << 3);
            unsigned h0, h1, e0, e1;
            split_pack(kv.x, kv.y, h0, e0);
            split_pack(kv.z, kv.w, h1, e1);
            *(uint2*)((char*)sKh + off) = make_uint2(h0, h1);
            *(uint2*)((char*)sKl + off) = make_uint2(e0, e1);
            split_pack(vv.x, vv.y, h0, e0);
            split_pack(vv.z, vv.w, h1, e1);
            *(uint2*)((char*)sVh + off) = make_uint2(h0, h1);
            *(uint2*)((char*)sVl + off) = make_uint2(e0, e1);
        }
        __syncthreads();

        float s[8][4];
        #pragma unroll
        for (int nd = 0; nd < 8; nd++)
            #pragma unroll
            for (int i = 0; i < 4; i++) s[nd][i] = 0.f;

        #pragma unroll
        for (int ko = 0; ko < 4; ko++) {
            #pragma unroll
            for (int nd2 = 0; nd2 < 4; nd2++) {
                int row = nd2 * 16 + l7 + ((lane >> 4) << 3);
                int ch  = 2 * ko + ((lane >> 3) & 1);
                uint32_t ad = (uint32_t)((row << 7) + ((ch ^ (row & 7)) << 4));
                unsigned rkh[4], rkl[4];
                ldsm_x4(rkh, aKh + ad);
                ldsm_x4(rkl, aKl + ad);
                mma_bf16(s[2 * nd2],     qh[ko], &rkh[0], s[2 * nd2]);
                mma_bf16(s[2 * nd2],     qh[ko], &rkl[0], s[2 * nd2]);
                mma_bf16(s[2 * nd2],     ql[ko], &rkh[0], s[2 * nd2]);
                mma_bf16(s[2 * nd2 + 1], qh[ko], &rkh[2], s[2 * nd2 + 1]);
                mma_bf16(s[2 * nd2 + 1], qh[ko], &rkl[2], s[2 * nd2 + 1]);
                mma_bf16(s[2 * nd2 + 1], ql[ko], &rkh[2], s[2 * nd2 + 1]);
            }
        }

        if (kt == qt) {
            const int r0 = w * 16 + g;
            const int r1 = r0 + 8;
            #pragma unroll
            for (int nd = 0; nd < 8; nd++) {
                int c0 = nd * 8 + 2 * t4;
                if (c0 > r0)     s[nd][0] = -1e30f;
                if (c0 + 1 > r0) s[nd][1] = -1e30f;
                if (c0 > r1)     s[nd][2] = -1e30f;
                if (c0 + 1 > r1) s[nd][3] = -1e30f;
            }
        }

        float mx0 = -1e30f, mx1 = -1e30f;
        #pragma unroll
        for (int nd = 0; nd < 8; nd++) {
            mx0 = fmaxf(mx0, fmaxf(s[nd][0], s[nd][1]));
            mx1 = fmaxf(mx1, fmaxf(s[nd][2], s[nd][3]));
        }
        mx0 = fmaxf(mx0, __shfl_xor_sync(0xffffffffu, mx0, 1));
        mx0 = fmaxf(mx0, __shfl_xor_sync(0xffffffffu, mx0, 2));
        mx1 = fmaxf(mx1, __shfl_xor_sync(0xffffffffu, mx1, 1));
        mx1 = fmaxf(mx1, __shfl_xor_sync(0xffffffffu, mx1, 2));
        float mn0 = fmaxf(m0, mx0), mn1 = fmaxf(m1, mx1);
        float c0 = __expf(m0 - mn0), c1 = __expf(m1 - mn1);
        m0 = mn0; m1 = mn1;
        l0 *= c0;  l1 *= c1;
        #pragma unroll
        for (int nd = 0; nd < 8; nd++) {
            out[nd][0] *= c0; out[nd][1] *= c0;
            out[nd][2] *= c1; out[nd][3] *= c1;
        }

        unsigned ph[4][4], pl[4][4];
        #pragma unroll
        for (int nd = 0; nd < 8; nd++) {
            float p0 = __expf(s[nd][0] - m0);
            float p1 = __expf(s[nd][1] - m0);
            float p2 = __expf(s[nd][2] - m1);
            float p3 = __expf(s[nd][3] - m1);
            l0 += p0 + p1;
            l1 += p2 + p3;
            const int ko = nd >> 1, rr = (nd & 1) * 2;
            split_pack(p0, p1, ph[ko][rr],     pl[ko][rr]);
            split_pack(p2, p3, ph[ko][rr + 1], pl[ko][rr + 1]);
        }

        #pragma unroll
        for (int ko = 0; ko < 4; ko++) {
            #pragma unroll
            for (int nd2 = 0; nd2 < 4; nd2++) {
                int row = ko * 16 + l7 + (((lane >> 3) & 1) << 3);
                int ch  = 2 * nd2 + (lane >> 4);
                uint32_t ad = (uint32_t)((row << 7) + ((ch ^ (row & 7)) << 4));
                unsigned rvh[4], rvl[4];
                ldsm_x4_t(rvh, aVh + ad);
                ldsm_x4_t(rvl, aVl + ad);
                mma_bf16(out[2 * nd2],     ph[ko], &rvh[0], out[2 * nd2]);
                mma_bf16(out[2 * nd2],     ph[ko], &rvl[0], out[2 * nd2]);
                mma_bf16(out[2 * nd2],     pl[ko], &rvh[0], out[2 * nd2]);
                mma_bf16(out[2 * nd2 + 1], ph[ko], &rvh[2], out[2 * nd2 + 1]);
                mma_bf16(out[2 * nd2 + 1], ph[ko], &rvl[2], out[2 * nd2 + 1]);
                mma_bf16(out[2 * nd2 + 1], pl[ko], &rvh[2], out[2 * nd2 + 1]);
            }
        }
    }

    l0 += __shfl_xor_sync(0xffffffffu, l0, 1);
    l0 += __shfl_xor_sync(0xffffffffu, l0, 2);
    l1 += __shfl_xor_sync(0xffffffffu, l1, 1);
    l1 += __shfl_xor_sync(0xffffffffu, l1, 2);
    const float i0 = 1.0f / l0, i1 = 1.0f / l1;

    const size_t r0 = (size_t)(b * Sz + qt * 64 + w * 16 + g);
    const size_t r1 = r0 + 8;
    #pragma unroll
    for (int nd = 0; nd < 8; nd++) {
        const int col = h * DKz + nd * 8 + 2 * t4;
        {
            float v0 = out[nd][0] * i0, v1 = out[nd][1] * i0;
            __nv_bfloat162 hh, ll;
            split2(v0, v1, hh, ll);
            *(__nv_bfloat162*)(OH + r0 * Dz + col) = hh;
            *(__nv_bfloat162*)(OL + r0 * Dz + col) = ll;
        }
        {
            float v0 = out[nd][2] * i1, v1 = out[nd][3] * i1;
            __nv_bfloat162 hh, ll;
            split2(v0, v1, hh, ll);
            *(__nv_bfloat162*)(OH + r1 * Dz + col) = hh;
            *(__nv_bfloat162*)(OL + r1 * Dz + col) = ll;
        }
    }
}

// ---------------------------------------------------------------------------
// Launcher
// ---------------------------------------------------------------------------
extern "C" void kernel_launch(void* const* d_in, const int* in_sizes, int n_in,
                              void* d_out, int out_size)
{
    (void)in_sizes; (void)n_in; (void)out_size;

    const float* x   = (const float*)d_in[0];
    const float* wq  = (const float*)d_in[1];
    const float* wk  = (const float*)d_in[2];
    const float* wv  = (const float*)d_in[3];
    const float* wo  = (const float*)d_in[4];
    const float* bo  = (const float*)d_in[5];
    const float* w1  = (const float*)d_in[6];
    const float* b1  = (const float*)d_in[7];
    const float* w2  = (const float*)d_in[8];
    const float* b2  = (const float*)d_in[9];
    const float* g1  = (const float*)d_in[10];
    const float* be1 = (const float*)d_in[11];
    const float* g2  = (const float*)d_in[12];
    const float* be2 = (const float*)d_in[13];
    float* out = (float*)d_out;

    __nv_bfloat16 *h1x, *atx, *h2x, *f1x, *wqkvx, *wox, *w1x, *w2x;
    float *qkv, *x2;
    cudaGetSymbolAddress((void**)&h1x,   g_h1x);
    cudaGetSymbolAddress((void**)&qkv,   g_qkv);
    cudaGetSymbolAddress((void**)&atx,   g_atx);
    cudaGetSymbolAddress((void**)&x2,    g_x2);
    cudaGetSymbolAddress((void**)&h2x,   g_h2x);
    cudaGetSymbolAddress((void**)&f1x,   g_f1x);
    cudaGetSymbolAddress((void**)&wqkvx, g_wqkvx);
    cudaGetSymbolAddress((void**)&wox,   g_wox);
    cudaGetSymbolAddress((void**)&w1x,   g_w1x);
    cudaGetSymbolAddress((void**)&w2x,   g_w2x);

    // 2-plane views (hi, lo)
    __nv_bfloat16* h1_h = h1x;
    __nv_bfloat16* h1_l = h1x + (size_t)Mz * Dz;
    __nv_bfloat16* at_h = atx;
    __nv_bfloat16* at_l = atx + (size_t)Mz * Dz;
    __nv_bfloat16* h2_h = h2x;
    __nv_bfloat16* h2_l = h2x + (size_t)Mz * Dz;
    __nv_bfloat16* f1_h = f1x;
    __nv_bfloat16* f1_l = f1x + (size_t)Mz * DFFz;

    cudaFuncSetAttribute(gemm_bf16_v8<0, false, false, false>,
                         cudaFuncAttributeMaxDynamicSharedMemorySize, V4_SMEM);
    cudaFuncSetAttribute(gemm_bf16_v8<0, false, true, true>,
                         cudaFuncAttributeMaxDynamicSharedMemorySize, V4_SMEM);
    cudaFuncSetAttribute(gemm_bf16_v8<2, true, true, false>,
                         cudaFuncAttributeMaxDynamicSharedMemorySize, V4_SMEM);

    // expand weights: fused QKV block [3072 x 3072], others standalone
    {
        int nDD = (Dz * Dz) / 4;
        int nDF = (Dz * DFFz) / 4;
        wexpand_kernel<<<(nDD + 255) / 256, 256>>>(wq, wqkvx, Dz, Dz, 3 * Dz, 0);
        wexpand_kernel<<<(nDD + 255) / 256, 256>>>(wk, wqkvx, Dz, Dz, 3 * Dz, Dz);
        wexpand_kernel<<<(nDD + 255) / 256, 256>>>(wv, wqkvx, Dz, Dz, 3 * Dz, 2 * Dz);
        wexpand_kernel<<<(nDD + 255) / 256, 256>>>(wo, wox, Dz, Dz, Dz, 0);
        wexpand_kernel<<<(nDF + 255) / 256, 256>>>(w1, w1x, Dz, DFFz, DFFz, 0);
        wexpand_kernel<<<(nDF + 255) / 256, 256>>>(w2, w2x, DFFz, Dz, Dz, 0);
    }

    // LN1 -> 2-plane A
    ln_split_kernel<<<Mz, 256>>>(x, g1, be1, h1_h, h1_l);
    // fused QKV projection: [M,3072] = h1 @ wqkv (fp32 out)
    gemm_bf16_v8<0, false, false, false>
        <<<dim3(24, Mz / 128), 128, V4_SMEM>>>(h1_h, h1_l, wqkvx, nullptr, nullptr,
                                               qkv, nullptr, 3 * Dz, Dz);
    // causal attention -> 2-plane output
    attn_mma_kernel<<<dim3(Sz / 64, Bz * Hz), 128>>>(qkv, at_h, at_l);
    // output projection + bias + residual(x)
    gemm_bf16_v8<0, false, true, true>
        <<<dim3(8, Mz / 128), 128, V4_SMEM>>>(at_h, at_l, wox, bo, x,
                                              x2, nullptr, Dz, Dz);
    // LN2 -> 2-plane A
    ln_split_kernel<<<Mz, 256>>>(x2, g2, be2, h2_h, h2_l);
    // FF1 + bias + exact GELU -> 2-plane output
    gemm_bf16_v8<2, true, true, false>
        <<<dim3(32, Mz / 128), 128, V4_SMEM>>>(h2_h, h2_l, w1x, b1, nullptr,
                                               f1_h, f1_l, DFFz, Dz);
    // FF2 + bias + residual(x2) -> final output
    gemm_bf16_v8<0, false, true, true>
        <<<dim3(8, Mz / 128), 128, V4_SMEM>>>(f1_h, f1_l, w2x, b2, x2,
                                              out, nullptr, Dz, DFFz);
}

// round 16
// speedup vs baseline: 1.0121x; 1.0121x over previous
#include <cuda_runtime.h>
#include <cuda_bf16.h>
#include <math.h>
#include <stddef.h>
#include <stdint.h>

// Problem dimensions (fixed by the reference)
#define Bz   4
#define Sz   2048
#define Dz   1024
#define Hz   16
#define DKz  64
#define DFFz 4096
#define Mz   (Bz * Sz)   // 8192 rows
#define QS   (3 * Dz)    // fused qkv row stride

// ---------------------------------------------------------------------------
// Scratch buffers. bf16x3 split GEMM along K:
//   A expanded [M, 3K] = [Ah | Ah | Al]
//   B expanded [3K, N] = [Bh ; Bl ; Bh]
// ---------------------------------------------------------------------------
static __device__ __nv_bfloat16 g_h1x[(size_t)Mz * 3 * Dz];
static __device__ float         g_qkv[(size_t)Mz * 3 * Dz];
static __device__ __nv_bfloat16 g_atx[(size_t)Mz * 3 * Dz];
static __device__ float         g_x2 [(size_t)Mz * Dz];
static __device__ __nv_bfloat16 g_h2x[(size_t)Mz * 3 * Dz];
static __device__ __nv_bfloat16 g_f1x[(size_t)Mz * 3 * DFFz];
static __device__ __nv_bfloat16 g_wqkvx[(size_t)(3 * Dz) * (3 * Dz)];
static __device__ __nv_bfloat16 g_wox[(size_t)(3 * Dz) * Dz];
static __device__ __nv_bfloat16 g_w1x[(size_t)(3 * Dz) * DFFz];
static __device__ __nv_bfloat16 g_w2x[(size_t)(3 * DFFz) * Dz];

// ---------------------------------------------------------------------------
// helpers
// ---------------------------------------------------------------------------
__device__ __forceinline__ float gelu_exact(float x)
{
    return 0.5f * x * (1.0f + erff(x * 0.70710678118654752440f));
}

__device__ __forceinline__ void split2(float y0, float y1,
                                       __nv_bfloat162& hh, __nv_bfloat162& ll)
{
    __nv_bfloat16 h0 = __float2bfloat16(y0);
    __nv_bfloat16 h1 = __float2bfloat16(y1);
    __nv_bfloat16 l0 = __float2bfloat16(y0 - __bfloat162float(h0));
    __nv_bfloat16 l1 = __float2bfloat16(y1 - __bfloat162float(h1));
    hh = __halves2bfloat162(h0, h1);
    ll = __halves2bfloat162(l0, l1);
}

__device__ __forceinline__ void split_pack(float a, float b, unsigned& hi, unsigned& lo)
{
    __nv_bfloat16 ha = __float2bfloat16(a);
    __nv_bfloat16 hb = __float2bfloat16(b);
    float ra = a - __bfloat162float(ha);
    float rb = b - __bfloat162float(hb);
    __nv_bfloat162 th = __halves2bfloat162(ha, hb);
    __nv_bfloat162 tl = __halves2bfloat162(__float2bfloat16(ra), __float2bfloat16(rb));
    hi = *(unsigned*)&th;
    lo = *(unsigned*)&tl;
}

__device__ __forceinline__ void ldsm_x4(unsigned* r, uint32_t addr)
{
    asm volatile("ldmatrix.sync.aligned.m8n8.x4.shared.b16 {%0,%1,%2,%3}, [%4];\n"
                 : "=r"(r[0]), "=r"(r[1]), "=r"(r[2]), "=r"(r[3]) : "r"(addr));
}
__device__ __forceinline__ void ldsm_x4_t(unsigned* r, uint32_t addr)
{
    asm volatile("ldmatrix.sync.aligned.m8n8.x4.trans.shared.b16 {%0,%1,%2,%3}, [%4];\n"
                 : "=r"(r[0]), "=r"(r[1]), "=r"(r[2]), "=r"(r[3]) : "r"(addr));
}
__device__ __forceinline__ void mma_bf16(float* d, const unsigned* a,
                                         const unsigned* b, const float* c)
{
    asm volatile(
        "mma.sync.aligned.m16n8k16.row.col.f32.bf16.bf16.f32 "
        "{%0,%1,%2,%3}, {%4,%5,%6,%7}, {%8,%9}, {%10,%11,%12,%13};\n"
        : "=f"(d[0]), "=f"(d[1]), "=f"(d[2]), "=f"(d[3])
        : "r"(a[0]), "r"(a[1]), "r"(a[2]), "r"(a[3]), "r"(b[0]), "r"(b[1]),
          "f"(c[0]), "f"(c[1]), "f"(c[2]), "f"(c[3]));
}
__device__ __forceinline__ void cp_async16(uint32_t dst, const void* src)
{
    asm volatile("cp.async.cg.shared.global [%0], [%1], 16;\n"
                 :: "r"(dst), "l"(src) : "memory");
}
__device__ __forceinline__ void cp_commit()
{
    asm volatile("cp.async.commit_group;\n" ::: "memory");
}

// ---------------------------------------------------------------------------
// Weight expansion: W[K,N] fp32 -> Wx[(3K) x ldN] bf16 at column offset n0,
// segments [hi;lo;hi].
// ---------------------------------------------------------------------------
__device__ __forceinline__ void wexpand_body(const float* __restrict__ W,
                                             __nv_bfloat16* __restrict__ Wx,
                                             int K, int N, int ldN, int n0,
                                             size_t idx)
{
    size_t e = idx << 2;
    int k = (int)(e / N);
    int n = (int)(e % N) + n0;
    float4 w = *(const float4*)(W + e);
    __nv_bfloat162 hh0, ll0, hh1, ll1;
    split2(w.x, w.y, hh0, ll0);
    split2(w.z, w.w, hh1, ll1);
    size_t b0 = (size_t)k * ldN + n;
    size_t b1 = ((size_t)K + k) * ldN + n;
    size_t b2 = ((size_t)2 * K + k) * ldN + n;
    *(__nv_bfloat162*)(Wx + b0)     = hh0;
    *(__nv_bfloat162*)(Wx + b0 + 2) = hh1;
    *(__nv_bfloat162*)(Wx + b1)     = ll0;
    *(__nv_bfloat162*)(Wx + b1 + 2) = ll1;
    *(__nv_bfloat162*)(Wx + b2)     = hh0;
    *(__nv_bfloat162*)(Wx + b2 + 2) = hh1;
}

__global__ __launch_bounds__(256)
void wexpand_kernel(const float* __restrict__ W, __nv_bfloat16* __restrict__ Wx,
                    int K, int N, int ldN, int n0)
{
    size_t idx = (size_t)blockIdx.x * blockDim.x + threadIdx.x;
    size_t total = ((size_t)K * N) >> 2;
    if (idx >= total) return;
    wexpand_body(W, Wx, K, N, ldN, n0, idx);
}

// fused QKV expansion: blockIdx.y selects wq/wk/wv, writing column block y*Dz
__global__ __launch_bounds__(256)
void wexpand_qkv_kernel(const float* __restrict__ wq, const float* __restrict__ wk,
                        const float* __restrict__ wv, __nv_bfloat16* __restrict__ Wx)
{
    size_t idx = (size_t)blockIdx.x * blockDim.x + threadIdx.x;
    size_t total = ((size_t)Dz * Dz) >> 2;
    if (idx >= total) return;
    const float* W = (blockIdx.y == 0) ? wq : (blockIdx.y == 1) ? wk : wv;
    wexpand_body(W, Wx, Dz, Dz, 3 * Dz, blockIdx.y * Dz, idx);
}

// ---------------------------------------------------------------------------
// LayerNorm + expand: out [row][3D] = [hi | hi | lo]
// ---------------------------------------------------------------------------
__global__ __launch_bounds__(256)
void ln_expand_kernel(const float* __restrict__ x, const float* __restrict__ g,
                      const float* __restrict__ bt, __nv_bfloat16* __restrict__ out)
{
    const int row = blockIdx.x;
    const int tid = threadIdx.x;
    const float4* xr = (const float4*)(x + (size_t)row * Dz);
    float4 v = xr[tid];

    float s  = v.x + v.y + v.z + v.w;
    float s2 = v.x * v.x + v.y * v.y + v.z * v.z + v.w * v.w;
    #pragma unroll
    for (int o = 16; o > 0; o >>= 1) {
        s  += __shfl_xor_sync(0xffffffffu, s,  o);
        s2 += __shfl_xor_sync(0xffffffffu, s2, o);
    }
    __shared__ float ws[8], ws2[8];
    const int wid = tid >> 5, lane = tid & 31;
    if (lane == 0) { ws[wid] = s; ws2[wid] = s2; }
    __syncthreads();
    __shared__ float s_mean, s_inv;
    if (tid == 0) {
        float a = 0.f, b = 0.f;
        #pragma unroll
        for (int i = 0; i < 8; i++) { a += ws[i]; b += ws2[i]; }
        float mean = a * (1.0f / Dz);
        float var  = b * (1.0f / Dz) - mean * mean;
        s_mean = mean;
        s_inv  = rsqrtf(var + 1e-5f);
    }
    __syncthreads();
    const float mean = s_mean, inv = s_inv;

    float4 gg = ((const float4*)g)[tid];
    float4 bb = ((const float4*)bt)[tid];
    float y0 = (v.x - mean) * inv * gg.x + bb.x;
    float y1 = (v.y - mean) * inv * gg.y + bb.y;
    float y2 = (v.z - mean) * inv * gg.z + bb.z;
    float y3 = (v.w - mean) * inv * gg.w + bb.w;

    __nv_bfloat162 hh0, ll0, hh1, ll1;
    split2(y0, y1, hh0, ll0);
    split2(y2, y3, hh1, ll1);
    const int col = tid * 4;
    __nv_bfloat16* o = out + (size_t)row * (3 * Dz) + col;
    *(__nv_bfloat162*)(o)              = hh0;
    *(__nv_bfloat162*)(o + 2)          = hh1;
    *(__nv_bfloat162*)(o + Dz)         = hh0;
    *(__nv_bfloat162*)(o + Dz + 2)     = hh1;
    *(__nv_bfloat162*)(o + 2 * Dz)     = ll0;
    *(__nv_bfloat162*)(o + 2 * Dz + 2) = ll1;
}

// ---------------------------------------------------------------------------
// bf16 tensor-core GEMM v4 (measured-best geometry):
// CTA tile 128x128, 128 threads (4 warps, 2Mx2N), warp tile 64x64, BK=32,
// 4-stage cp.async ring, 2 CTAs/SM, two barriers per K-iteration,
// loads issued BEFORE wait.
// OUTMODE 0: fp32 C (+bias)(+gelu)(+res); OUTMODE 1: expanded bf16 [M,3N].
// ---------------------------------------------------------------------------
#define V4_STAGES 4
#define V4_ASTAGE 8192
#define V4_STAGE  16384
#define V4_SMEM   (V4_STAGES * V4_STAGE + 1024)   // 66560

template<int OUTMODE, bool GELU, bool BIAS, bool RES>
__global__ __launch_bounds__(128, 2)
void gemm_bf16_v4(const __nv_bfloat16* __restrict__ A, const __nv_bfloat16* __restrict__ B,
                  const float* __restrict__ bias, const float* __restrict__ res,
                  void* __restrict__ Cout, int Ni, int Kp)
{
    extern __shared__ char dsm[];
    const uint32_t base0 = ((uint32_t)__cvta_generic_to_shared(dsm) + 1023u) & ~1023u;

    const int tid = threadIdx.x;
    const int lane = tid & 31;
    const int wid = tid >> 5;
    const int warp_m = wid & 1;
    const int warp_n = wid >> 1;
    const int bm = blockIdx.y * 128;
    const int bn = blockIdx.x * 128;

    const int l7  = lane & 7;
    const int l8  = (lane >> 3) & 1;
    const int l16 = lane >> 4;

    float acc[4][8][4];
    #pragma unroll
    for (int mt = 0; mt < 4; mt++)
        #pragma unroll
        for (int nt = 0; nt < 8; nt++)
            #pragma unroll
            for (int i = 0; i < 4; i++) acc[mt][nt][i] = 0.f;

    auto load_stage = [&](int kt) {
        const uint32_t base = base0 + (kt & (V4_STAGES - 1)) * V4_STAGE;
        #pragma unroll
        for (int i = 0; i < 4; i++) {
            int idx = i * 128 + tid;
            int m = idx >> 2, c = idx & 3;
            const void* src = A + (size_t)(bm + m) * Kp + kt * 32 + c * 8;
            cp_async16(base + (m << 6) + ((c ^ ((m >> 1) & 3)) << 4), src);
        }
        #pragma unroll
        for (int i = 0; i < 4; i++) {
            int idx = i * 128 + tid;
            int k = idx >> 4, c = idx & 15;
            const void* src = B + (size_t)(kt * 32 + k) * Ni + bn + c * 8;
            cp_async16(base + V4_ASTAGE + (k << 8) + ((c ^ (k & 7)) << 4), src);
        }
        cp_commit();
    };

    const int NK = Kp / 32;
    load_stage(0); load_stage(1); load_stage(2);

    for (int kt = 0; kt < NK; kt++) {
        if (kt + 3 < NK) load_stage(kt + 3);
        const int rem = NK - 1 - kt;
        if (rem >= 3)      asm volatile("cp.async.wait_group 3;\n" ::: "memory");
        else if (rem == 2) asm volatile("cp.async.wait_group 2;\n" ::: "memory");
        else if (rem == 1) asm volatile("cp.async.wait_group 1;\n" ::: "memory");
        else               asm volatile("cp.async.wait_group 0;\n" ::: "memory");
        __syncthreads();

        const uint32_t sa = base0 + (kt & (V4_STAGES - 1)) * V4_STAGE;
        const uint32_t sb = sa + V4_ASTAGE;
        #pragma unroll
        for (int ks = 0; ks < 2; ks++) {
            unsigned ra[4][4], rb[4][4];
            #pragma unroll
            for (int mt = 0; mt < 4; mt++) {
                int row = warp_m * 64 + mt * 16 + l7 + l8 * 8;
                int c   = ks * 2 + l16;
                ldsm_x4(ra[mt], sa + (row << 6) + ((c ^ ((row >> 1) & 3)) << 4));
            }
            #pragma unroll
            for (int p = 0; p < 4; p++) {
                int k = ks * 16 + l7 + l8 * 8;
                int c = warp_n * 8 + p * 2 + l16;
                ldsm_x4_t(rb[p], sb + (k << 8) + ((c ^ (k & 7)) << 4));
            }
            #pragma unroll
            for (int mt = 0; mt < 4; mt++)
                #pragma unroll
                for (int nt = 0; nt < 8; nt++)
                    mma_bf16(acc[mt][nt], ra[mt], &rb[nt >> 1][(nt & 1) * 2], acc[mt][nt]);
        }
        __syncthreads();
    }

    // epilogue
    const int g = lane >> 2, t = lane & 3;
    #pragma unroll
    for (int mt = 0; mt < 4; mt++) {
        #pragma unroll
        for (int nt = 0; nt < 8; nt++) {
            const int col = bn + warp_n * 64 + nt * 8 + 2 * t;
            #pragma unroll
            for (int half = 0; half < 2; half++) {
                const int r = bm + warp_m * 64 + mt * 16 + g + half * 8;
                float v0 = acc[mt][nt][half * 2 + 0];
                float v1 = acc[mt][nt][half * 2 + 1];
                if (BIAS) { v0 += bias[col]; v1 += bias[col + 1]; }
                if (GELU) { v0 = gelu_exact(v0); v1 = gelu_exact(v1); }
                if (RES) {
                    const float* rp = res + (size_t)r * Ni + col;
                    v0 += rp[0]; v1 += rp[1];
                }
                if (OUTMODE == 0) {
                    float2 o; o.x = v0; o.y = v1;
                    *(float2*)((float*)Cout + (size_t)r * Ni + col) = o;
                } else {
                    __nv_bfloat162 hh, ll;
                    split2(v0, v1, hh, ll);
                    __nv_bfloat16* Cb = (__nv_bfloat16*)Cout;
                    size_t b = (size_t)r * (3 * Ni) + col;
                    *(__nv_bfloat162*)(Cb + b)          = hh;
                    *(__nv_bfloat162*)(Cb + b + Ni)     = hh;
                    *(__nv_bfloat162*)(Cb + b + 2 * Ni) = ll;
                }
            }
        }
    }
}

// ---------------------------------------------------------------------------
// Tensor-core causal flash attention (bf16x3 split, fp32 softmax).
// 64 queries per CTA (4 warps), K/V tiles of 64 keys.
// Reads fused qkv [M, 3D]: Q at +0, K at +D, V at +2D. Writes expanded bf16.
// ---------------------------------------------------------------------------
__global__ __launch_bounds__(128)
void attn_mma_kernel(const float* __restrict__ QKV, __nv_bfloat16* __restrict__ O)
{
    const int qt  = (gridDim.x - 1) - blockIdx.x;
    const int bh  = blockIdx.y;
    const int b   = bh >> 4;
    const int h   = bh & 15;
    const int tid = threadIdx.x;
    const int w   = tid >> 5;
    const int lane = tid & 31;
    const int g   = lane >> 2;
    const int t4  = lane & 3;
    const int l7  = lane & 7;

    __shared__ __align__(128) __nv_bfloat16 sKh[64 * 64];
    __shared__ __align__(128) __nv_bfloat16 sKl[64 * 64];
    __shared__ __align__(128) __nv_bfloat16 sVh[64 * 64];
    __shared__ __align__(128) __nv_bfloat16 sVl[64 * 64];
    const uint32_t aKh = (uint32_t)__cvta_generic_to_shared(sKh);
    const uint32_t aKl = (uint32_t)__cvta_generic_to_shared(sKl);
    const uint32_t aVh = (uint32_t)__cvta_generic_to_shared(sVh);
    const uint32_t aVl = (uint32_t)__cvta_generic_to_shared(sVl);

    unsigned qh[4][4], ql[4][4];
    {
        const float* Qw = QKV + ((size_t)(b * Sz + qt * 64 + w * 16)) * QS + h * DKz;
        #pragma unroll
        for (int ko = 0; ko < 4; ko++) {
            #pragma unroll
            for (int rh = 0; rh < 2; rh++) {
                const float* rp = Qw + (size_t)(rh * 8 + g) * QS + ko * 16 + 2 * t4;
                float2 lo = *(const float2*)rp;
                float2 hi = *(const float2*)(rp + 8);
                split_pack(lo.x * 0.125f, lo.y * 0.125f, qh[ko][rh],     ql[ko][rh]);
                split_pack(hi.x * 0.125f, hi.y * 0.125f, qh[ko][2 + rh], ql[ko][2 + rh]);
            }
        }
    }

    float out[8][4];
    #pragma unroll
    for (int nd = 0; nd < 8; nd++)
        #pragma unroll
        for (int i = 0; i < 4; i++) out[nd][i] = 0.f;
    float m0 = -1e30f, m1 = -1e30f, l0 = 0.f, l1 = 0.f;

    const float* Kb = QKV + ((size_t)(b * Sz)) * QS + Dz + h * DKz;
    const float* Vb = QKV + ((size_t)(b * Sz)) * QS + 2 * Dz + h * DKz;

    for (int kt = 0; kt <= qt; kt++) {
        __syncthreads();
        const float* Kt = Kb + (size_t)kt * 64 * QS;
        const float* Vt = Vb + (size_t)kt * 64 * QS;
        #pragma unroll
        for (int i = 0; i < 8; i++) {
            int idx = i * 128 + tid;
            int row = idx >> 4, c4 = idx & 15;
            const size_t go = (size_t)row * QS + c4 * 4;
            float4 kv = *(const float4*)(Kt + go);
            float4 vv = *(const float4*)(Vt + go);
            uint32_t off = (row << 7) + ((((c4 >> 1) ^ (row & 7)) << 4)) + ((c4 & 1) << 3);
            unsigned h0, h1, e0, e1;
            split_pack(kv.x, kv.y, h0, e0);
            split_pack(kv.z, kv.w, h1, e1);
            *(uint2*)((char*)sKh + off) = make_uint2(h0, h1);
            *(uint2*)((char*)sKl + off) = make_uint2(e0, e1);
            split_pack(vv.x, vv.y, h0, e0);
            split_pack(vv.z, vv.w, h1, e1);
            *(uint2*)((char*)sVh + off) = make_uint2(h0, h1);
            *(uint2*)((char*)sVl + off) = make_uint2(e0, e1);
        }
        __syncthreads();

        float s[8][4];
        #pragma unroll
        for (int nd = 0; nd < 8; nd++)
            #pragma unroll
            for (int i = 0; i < 4; i++) s[nd][i] = 0.f;

        #pragma unroll
        for (int ko = 0; ko < 4; ko++) {
            #pragma unroll
            for (int nd2 = 0; nd2 < 4; nd2++) {
                int row = nd2 * 16 + l7 + ((lane >> 4) << 3);
                int ch  = 2 * ko + ((lane >> 3) & 1);
                uint32_t ad = (uint32_t)((row << 7) + ((ch ^ (row & 7)) << 4));
                unsigned rkh[4], rkl[4];
                ldsm_x4(rkh, aKh + ad);
                ldsm_x4(rkl, aKl + ad);
                mma_bf16(s[2 * nd2],     qh[ko], &rkh[0], s[2 * nd2]);
                mma_bf16(s[2 * nd2],     qh[ko], &rkl[0], s[2 * nd2]);
                mma_bf16(s[2 * nd2],     ql[ko], &rkh[0], s[2 * nd2]);
                mma_bf16(s[2 * nd2 + 1], qh[ko], &rkh[2], s[2 * nd2 + 1]);
                mma_bf16(s[2 * nd2 + 1], qh[ko], &rkl[2], s[2 * nd2 + 1]);
                mma_bf16(s[2 * nd2 + 1], ql[ko], &rkh[2], s[2 * nd2 + 1]);
            }
        }

        if (kt == qt) {
            const int r0 = w * 16 + g;
            const int r1 = r0 + 8;
            #pragma unroll
            for (int nd = 0; nd < 8; nd++) {
                int c0 = nd * 8 + 2 * t4;
                if (c0 > r0)     s[nd][0] = -1e30f;
                if (c0 + 1 > r0) s[nd][1] = -1e30f;
                if (c0 > r1)     s[nd][2] = -1e30f;
                if (c0 + 1 > r1) s[nd][3] = -1e30f;
            }
        }

        float mx0 = -1e30f, mx1 = -1e30f;
        #pragma unroll
        for (int nd = 0; nd < 8; nd++) {
            mx0 = fmaxf(mx0, fmaxf(s[nd][0], s[nd][1]));
            mx1 = fmaxf(mx1, fmaxf(s[nd][2], s[nd][3]));
        }
        mx0 = fmaxf(mx0, __shfl_xor_sync(0xffffffffu, mx0, 1));
        mx0 = fmaxf(mx0, __shfl_xor_sync(0xffffffffu, mx0, 2));
        mx1 = fmaxf(mx1, __shfl_xor_sync(0xffffffffu, mx1, 1));
        mx1 = fmaxf(mx1, __shfl_xor_sync(0xffffffffu, mx1, 2));
        float mn0 = fmaxf(m0, mx0), mn1 = fmaxf(m1, mx1);
        float c0 = __expf(m0 - mn0), c1 = __expf(m1 - mn1);
        m0 = mn0; m1 = mn1;
        l0 *= c0;  l1 *= c1;
        #pragma unroll
        for (int nd = 0; nd < 8; nd++) {
            out[nd][0] *= c0; out[nd][1] *= c0;
            out[nd][2] *= c1; out[nd][3] *= c1;
        }

        unsigned ph[4][4], pl[4][4];
        #pragma unroll
        for (int nd = 0; nd < 8; nd++) {
            float p0 = __expf(s[nd][0] - m0);
            float p1 = __expf(s[nd][1] - m0);
            float p2 = __expf(s[nd][2] - m1);
            float p3 = __expf(s[nd][3] - m1);
            l0 += p0 + p1;
            l1 += p2 + p3;
            const int ko = nd >> 1, rr = (nd & 1) * 2;
            split_pack(p0, p1, ph[ko][rr],     pl[ko][rr]);
            split_pack(p2, p3, ph[ko][rr + 1], pl[ko][rr + 1]);
        }

        #pragma unroll
        for (int ko = 0; ko < 4; ko++) {
            #pragma unroll
            for (int nd2 = 0; nd2 < 4; nd2++) {
                int row = ko * 16 + l7 + (((lane >> 3) & 1) << 3);
                int ch  = 2 * nd2 + (lane >> 4);
                uint32_t ad = (uint32_t)((row << 7) + ((ch ^ (row & 7)) << 4));
                unsigned rvh[4], rvl[4];
                ldsm_x4_t(rvh, aVh + ad);
                ldsm_x4_t(rvl, aVl + ad);
                mma_bf16(out[2 * nd2],     ph[ko], &rvh[0], out[2 * nd2]);
                mma_bf16(out[2 * nd2],     ph[ko], &rvl[0], out[2 * nd2]);
                mma_bf16(out[2 * nd2],     pl[ko], &rvh[0], out[2 * nd2]);
                mma_bf16(out[2 * nd2 + 1], ph[ko], &rvh[2], out[2 * nd2 + 1]);
                mma_bf16(out[2 * nd2 + 1], ph[ko], &rvl[2], out[2 * nd2 + 1]);
                mma_bf16(out[2 * nd2 + 1], pl[ko], &rvh[2], out[2 * nd2 + 1]);
            }
        }
    }

    l0 += __shfl_xor_sync(0xffffffffu, l0, 1);
    l0 += __shfl_xor_sync(0xffffffffu, l0, 2);
    l1 += __shfl_xor_sync(0xffffffffu, l1, 1);
    l1 += __shfl_xor_sync(0xffffffffu, l1, 2);
    const float i0 = 1.0f / l0, i1 = 1.0f / l1;

    const size_t r0 = (size_t)(b * Sz + qt * 64 + w * 16 + g);
    const size_t r1 = r0 + 8;
    #pragma unroll
    for (int nd = 0; nd < 8; nd++) {
        const int col = h * DKz + nd * 8 + 2 * t4;
        {
            float v0 = out[nd][0] * i0, v1 = out[nd][1] * i0;
            __nv_bfloat162 hh, ll;
            split2(v0, v1, hh, ll);
            __nv_bfloat16* p = O + r0 * (3 * Dz) + col;
            *(__nv_bfloat162*)(p)          = hh;
            *(__nv_bfloat162*)(p + Dz)     = hh;
            *(__nv_bfloat162*)(p + 2 * Dz) = ll;
        }
        {
            float v0 = out[nd][2] * i1, v1 = out[nd][3] * i1;
            __nv_bfloat162 hh, ll;
            split2(v0, v1, hh, ll);
            __nv_bfloat16* p = O + r1 * (3 * Dz) + col;
            *(__nv_bfloat162*)(p)          = hh;
            *(__nv_bfloat162*)(p + Dz)     = hh;
            *(__nv_bfloat162*)(p + 2 * Dz) = ll;
        }
    }
}

// ---------------------------------------------------------------------------
// Launcher
// ---------------------------------------------------------------------------
extern "C" void kernel_launch(void* const* d_in, const int* in_sizes, int n_in,
                              void* d_out, int out_size)
{
    (void)in_sizes; (void)n_in; (void)out_size;

    const float* x   = (const float*)d_in[0];
    const float* wq  = (const float*)d_in[1];
    const float* wk  = (const float*)d_in[2];
    const float* wv  = (const float*)d_in[3];
    const float* wo  = (const float*)d_in[4];
    const float* bo  = (const float*)d_in[5];
    const float* w1  = (const float*)d_in[6];
    const float* b1  = (const float*)d_in[7];
    const float* w2  = (const float*)d_in[8];
    const float* b2  = (const float*)d_in[9];
    const float* g1  = (const float*)d_in[10];
    const float* be1 = (const float*)d_in[11];
    const float* g2  = (const float*)d_in[12];
    const float* be2 = (const float*)d_in[13];
    float* out = (float*)d_out;

    __nv_bfloat16 *h1x, *atx, *h2x, *f1x, *wqkvx, *wox, *w1x, *w2x;
    float *qkv, *x2;
    cudaGetSymbolAddress((void**)&h1x,   g_h1x);
    cudaGetSymbolAddress((void**)&qkv,   g_qkv);
    cudaGetSymbolAddress((void**)&atx,   g_atx);
    cudaGetSymbolAddress((void**)&x2,    g_x2);
    cudaGetSymbolAddress((void**)&h2x,   g_h2x);
    cudaGetSymbolAddress((void**)&f1x,   g_f1x);
    cudaGetSymbolAddress((void**)&wqkvx, g_wqkvx);
    cudaGetSymbolAddress((void**)&wox,   g_wox);
    cudaGetSymbolAddress((void**)&w1x,   g_w1x);
    cudaGetSymbolAddress((void**)&w2x,   g_w2x);

    cudaFuncSetAttribute(gemm_bf16_v4<0, false, false, false>,
                         cudaFuncAttributeMaxDynamicSharedMemorySize, V4_SMEM);
    cudaFuncSetAttribute(gemm_bf16_v4<0, false, true, true>,
                         cudaFuncAttributeMaxDynamicSharedMemorySize, V4_SMEM);
    cudaFuncSetAttribute(gemm_bf16_v4<1, true, true, false>,
                         cudaFuncAttributeMaxDynamicSharedMemorySize, V4_SMEM);

    // expand weights: fused QKV expansion (one launch), others standalone
    {
        int nDD = (Dz * Dz) / 4;
        int nDF = (Dz * DFFz) / 4;
        wexpand_qkv_kernel<<<dim3((nDD + 255) / 256, 3), 256>>>(wq, wk, wv, wqkvx);
        wexpand_kernel<<<(nDD + 255) / 256, 256>>>(wo, wox, Dz, Dz, Dz, 0);
        wexpand_kernel<<<(nDF + 255) / 256, 256>>>(w1, w1x, Dz, DFFz, DFFz, 0);
        wexpand_kernel<<<(nDF + 255) / 256, 256>>>(w2, w2x, DFFz, Dz, Dz, 0);
    }

    // LN1 -> expanded A
    ln_expand_kernel<<<Mz, 256>>>(x, g1, be1, h1x);
    // fused QKV projection: [M,3072] = h1x @ wqkv
    gemm_bf16_v4<0, false, false, false>
        <<<dim3(24, Mz / 128), 128, V4_SMEM>>>(h1x, wqkvx, nullptr, nullptr,
                                               qkv, 3 * Dz, 3 * Dz);
    // causal attention
    attn_mma_kernel<<<dim3(Sz / 64, Bz * Hz), 128>>>(qkv, atx);
    // output projection + bias + residual(x)
    gemm_bf16_v4<0, false, true, true>
        <<<dim3(8, Mz / 128), 128, V4_SMEM>>>(atx, wox, bo, x, x2, Dz, 3 * Dz);
    // LN2
    ln_expand_kernel<<<Mz, 256>>>(x2, g2, be2, h2x);
    // FF1 + bias + exact GELU -> expanded
    gemm_bf16_v4<1, true, true, false>
        <<<dim3(32, Mz / 128), 128, V4_SMEM>>>(h2x, w1x, b1, nullptr, f1x,
                                               DFFz, 3 * Dz);
    // FF2 + bias + residual(x2) -> final output
    gemm_bf16_v4<0, false, true, true>
        <<<dim3(8, Mz / 128), 128, V4_SMEM>>>(f1x, w2x, b2, x2, out, Dz, 3 * DFFz);
}